// round 1
// baseline (speedup 1.0000x reference)
#include <cuda_runtime.h>

// Problem constants
#define SEQ     2048
#define DMODEL  1024
#define NBATCH  2
#define NH      16
#define DH      64
#define MROWS   (NBATCH * SEQ)          // 4096

// Scratch (device globals: allocation-guard safe). 4 x 16MB.
__device__ float g_q[MROWS * DMODEL];
__device__ float g_k[MROWS * DMODEL];
__device__ float g_v[MROWS * DMODEL];
__device__ float g_ctx[MROWS * DMODEL];

// ---------------------------------------------------------------------------
// Kernel 1: fused QKV projection.  C = X @ W, written to [B*H, S, DH] layout.
// grid = (N/128, M/128, 3)   block = 256 threads, 8x8 register tile.
// z==0 -> Q (scaled by 1/sqrt(DH)=0.125), z==1 -> K, z==2 -> V.
// ---------------------------------------------------------------------------
__global__ __launch_bounds__(256) void qkv_gemm(
    const float* __restrict__ X,
    const float* __restrict__ Wq,
    const float* __restrict__ Wk,
    const float* __restrict__ Wv)
{
    __shared__ float As[8][128];
    __shared__ float Bs[8][128];

    const int bn = blockIdx.x * 128;
    const int bm = blockIdx.y * 128;

    const float* W; float* Out; float scale;
    if (blockIdx.z == 0)      { W = Wq; Out = g_q; scale = 0.125f; }
    else if (blockIdx.z == 1) { W = Wk; Out = g_k; scale = 1.0f;   }
    else                      { W = Wv; Out = g_v; scale = 1.0f;   }

    const int tid = threadIdx.x;
    const int tx = tid & 15;        // 16 col-threads
    const int ty = tid >> 4;        // 16 row-threads

    // A-tile loader: 128x8 floats, 1 float4 per thread
    const int arow = tid >> 1;
    const int acol = (tid & 1) << 2;
    // B-tile loader: 8x128 floats, 1 float4 per thread
    const int brow = tid >> 5;
    const int bcol = (tid & 31) << 2;

    const float* Ap = X + (bm + arow) * DMODEL + acol;
    const float* Bp = W + brow * DMODEL + bn + bcol;

    float acc[8][8];
    #pragma unroll
    for (int i = 0; i < 8; i++)
        #pragma unroll
        for (int j = 0; j < 8; j++) acc[i][j] = 0.0f;

    for (int k0 = 0; k0 < DMODEL; k0 += 8) {
        float4 a = *(const float4*)Ap;
        As[acol + 0][arow] = a.x;
        As[acol + 1][arow] = a.y;
        As[acol + 2][arow] = a.z;
        As[acol + 3][arow] = a.w;
        *(float4*)&Bs[brow][bcol] = *(const float4*)Bp;
        __syncthreads();

        #pragma unroll
        for (int kk = 0; kk < 8; kk++) {
            float rm[8], rn[8];
            *(float4*)&rm[0] = *(const float4*)&As[kk][ty * 8];
            *(float4*)&rm[4] = *(const float4*)&As[kk][ty * 8 + 4];
            *(float4*)&rn[0] = *(const float4*)&Bs[kk][tx * 8];
            *(float4*)&rn[4] = *(const float4*)&Bs[kk][tx * 8 + 4];
            #pragma unroll
            for (int i = 0; i < 8; i++)
                #pragma unroll
                for (int j = 0; j < 8; j++)
                    acc[i][j] += rm[i] * rn[j];
        }
        __syncthreads();
        Ap += 8;
        Bp += 8 * DMODEL;
    }

    // Write to [ (b*NH + h) * SEQ + s ] * DH + d
    #pragma unroll
    for (int i = 0; i < 8; i++) {
        int m = bm + ty * 8 + i;
        int b = m >> 11;            // /SEQ
        int s = m & (SEQ - 1);
        #pragma unroll
        for (int jj = 0; jj < 8; jj += 4) {
            int n = bn + tx * 8 + jj;
            int h = n >> 6;
            int d = n & (DH - 1);
            float4 o;
            o.x = acc[i][jj + 0] * scale;
            o.y = acc[i][jj + 1] * scale;
            o.z = acc[i][jj + 2] * scale;
            o.w = acc[i][jj + 3] * scale;
            *(float4*)&Out[(((b << 4) + h) * SEQ + s) * DH + d] = o;
        }
    }
}

// ---------------------------------------------------------------------------
// Kernel 2: flash-style attention (fp32 SIMT, NO mask — matches reference).
// grid = (SEQ/QT, B*NH), block = 256 threads.
// Q-tile 128 rows; loop K/V in tiles of 64; online softmax in registers.
// Thread (tx,ty): owns 8 q-rows (ty*8..) x 4 cols (tx*4..) in both GEMMs.
// ---------------------------------------------------------------------------
#define QT 128
#define KT 64
#define QSP 132                      // Qs pitch (pad: keeps fp4 align, kills bank conflicts)
#define KSP 68                       // Ks pitch
#define ATTN_SMEM ((DH*QSP + DH*KSP + QT*KT + KT*DH) * 4)

__global__ __launch_bounds__(256, 2) void attn_kernel()
{
    extern __shared__ float sm[];
    float* Qs = sm;                        // [DH][QSP]  (d-major, transposed)
    float* Ks = Qs + DH * QSP;             // [DH][KSP]  (d-major, transposed)
    float* Ps = Ks + DH * KSP;             // [QT][KT]   (row-major)
    float* Vs = Ps + QT * KT;              // [KT][DH]   (row-major)

    const int bh = blockIdx.y;
    const int q0 = blockIdx.x * QT;
    const float* Qb = g_q + bh * (SEQ * DH);
    const float* Kb = g_k + bh * (SEQ * DH);
    const float* Vb = g_v + bh * (SEQ * DH);

    const int tid = threadIdx.x;
    const int tx = tid & 15;
    const int ty = tid >> 4;

    // Load Q tile transposed: Qs[d][r]. 2048 float4's, 8 per thread.
    #pragma unroll
    for (int i = 0; i < 8; i++) {
        int idx4 = tid + i * 256;
        int r  = idx4 >> 4;
        int d0 = (idx4 & 15) << 2;
        float4 v = *(const float4*)(Qb + (q0 + r) * DH + d0);
        Qs[(d0 + 0) * QSP + r] = v.x;
        Qs[(d0 + 1) * QSP + r] = v.y;
        Qs[(d0 + 2) * QSP + r] = v.z;
        Qs[(d0 + 3) * QSP + r] = v.w;
    }

    float m_run[8], l_run[8], acc[8][4];
    #pragma unroll
    for (int a = 0; a < 8; a++) {
        m_run[a] = -1e30f;
        l_run[a] = 0.0f;
        acc[a][0] = acc[a][1] = acc[a][2] = acc[a][3] = 0.0f;
    }

    for (int k0 = 0; k0 < SEQ; k0 += KT) {
        __syncthreads();   // previous iter's reads of Ks/Vs/Ps done; Qs ready (1st iter)

        // Load K (transposed -> Ks[d][k]) and V (natural -> Vs[k][d]).
        #pragma unroll
        for (int i = 0; i < 4; i++) {
            int idx4 = tid + i * 256;
            int r  = idx4 >> 4;
            int d0 = (idx4 & 15) << 2;
            float4 kv = *(const float4*)(Kb + (k0 + r) * DH + d0);
            Ks[(d0 + 0) * KSP + r] = kv.x;
            Ks[(d0 + 1) * KSP + r] = kv.y;
            Ks[(d0 + 2) * KSP + r] = kv.z;
            Ks[(d0 + 3) * KSP + r] = kv.w;
            *(float4*)&Vs[r * DH + d0] = *(const float4*)(Vb + (k0 + r) * DH + d0);
        }
        __syncthreads();

        // GEMM1: s[8][4] = Q_tile @ K_tile^T   (scale already folded into Q)
        float s[8][4];
        #pragma unroll
        for (int a = 0; a < 8; a++)
            s[a][0] = s[a][1] = s[a][2] = s[a][3] = 0.0f;

        #pragma unroll 8
        for (int d = 0; d < DH; d++) {
            float rq[8], rk[4];
            *(float4*)&rq[0] = *(const float4*)&Qs[d * QSP + ty * 8];
            *(float4*)&rq[4] = *(const float4*)&Qs[d * QSP + ty * 8 + 4];
            *(float4*)&rk[0] = *(const float4*)&Ks[d * KSP + tx * 4];
            #pragma unroll
            for (int a = 0; a < 8; a++)
                #pragma unroll
                for (int j = 0; j < 4; j++)
                    s[a][j] += rq[a] * rk[j];
        }

        // Online softmax update. Row stats replicated across the 16 tx lanes.
        #pragma unroll
        for (int a = 0; a < 8; a++) {
            float mt = fmaxf(fmaxf(s[a][0], s[a][1]), fmaxf(s[a][2], s[a][3]));
            #pragma unroll
            for (int o = 8; o > 0; o >>= 1)
                mt = fmaxf(mt, __shfl_xor_sync(0xffffffffu, mt, o));
            float mn = fmaxf(m_run[a], mt);
            float f  = __expf(m_run[a] - mn);
            float ssum = 0.0f;
            #pragma unroll
            for (int j = 0; j < 4; j++) {
                float p = __expf(s[a][j] - mn);
                s[a][j] = p;
                ssum += p;
            }
            #pragma unroll
            for (int o = 8; o > 0; o >>= 1)
                ssum += __shfl_xor_sync(0xffffffffu, ssum, o);
            l_run[a] = l_run[a] * f + ssum;
            m_run[a] = mn;
            acc[a][0] *= f; acc[a][1] *= f; acc[a][2] *= f; acc[a][3] *= f;
        }

        // Stage P to shared (row-major, conflict-free float4 stores)
        #pragma unroll
        for (int a = 0; a < 8; a++) {
            float4 p4 = make_float4(s[a][0], s[a][1], s[a][2], s[a][3]);
            *(float4*)&Ps[(ty * 8 + a) * KT + tx * 4] = p4;
        }
        __syncthreads();

        // GEMM2: acc += P_tile @ V_tile
        #pragma unroll 4
        for (int c0 = 0; c0 < KT; c0 += 4) {
            float4 v0 = *(const float4*)&Vs[(c0 + 0) * DH + tx * 4];
            float4 v1 = *(const float4*)&Vs[(c0 + 1) * DH + tx * 4];
            float4 v2 = *(const float4*)&Vs[(c0 + 2) * DH + tx * 4];
            float4 v3 = *(const float4*)&Vs[(c0 + 3) * DH + tx * 4];
            #pragma unroll
            for (int a = 0; a < 8; a++) {
                float4 p = *(const float4*)&Ps[(ty * 8 + a) * KT + c0];
                acc[a][0] += p.x * v0.x + p.y * v1.x + p.z * v2.x + p.w * v3.x;
                acc[a][1] += p.x * v0.y + p.y * v1.y + p.z * v2.y + p.w * v3.y;
                acc[a][2] += p.x * v0.z + p.y * v1.z + p.z * v2.z + p.w * v3.z;
                acc[a][3] += p.x * v0.w + p.y * v1.w + p.z * v2.w + p.w * v3.w;
            }
        }
    }

    // Epilogue: ctx[(b*SEQ + q)*DMODEL + h*DH + d] = acc / l
    const int b = bh >> 4;
    const int h = bh & 15;
    #pragma unroll
    for (int a = 0; a < 8; a++) {
        int r = q0 + ty * 8 + a;
        float inv = 1.0f / l_run[a];
        float4 o;
        o.x = acc[a][0] * inv;
        o.y = acc[a][1] * inv;
        o.z = acc[a][2] * inv;
        o.w = acc[a][3] * inv;
        *(float4*)&g_ctx[(b * SEQ + r) * DMODEL + h * DH + tx * 4] = o;
    }
}

// ---------------------------------------------------------------------------
// Kernel 3: output projection + bias.  out = ctx @ Wo + bo  (row-major)
// ---------------------------------------------------------------------------
__global__ __launch_bounds__(256) void out_gemm(
    const float* __restrict__ Wo,
    const float* __restrict__ bo,
    float* __restrict__ out)
{
    __shared__ float As[8][128];
    __shared__ float Bs[8][128];

    const int bn = blockIdx.x * 128;
    const int bm = blockIdx.y * 128;

    const int tid = threadIdx.x;
    const int tx = tid & 15;
    const int ty = tid >> 4;

    const int arow = tid >> 1;
    const int acol = (tid & 1) << 2;
    const int brow = tid >> 5;
    const int bcol = (tid & 31) << 2;

    const float* Ap = g_ctx + (bm + arow) * DMODEL + acol;
    const float* Bp = Wo + brow * DMODEL + bn + bcol;

    float acc[8][8];
    #pragma unroll
    for (int i = 0; i < 8; i++)
        #pragma unroll
        for (int j = 0; j < 8; j++) acc[i][j] = 0.0f;

    for (int k0 = 0; k0 < DMODEL; k0 += 8) {
        float4 a = *(const float4*)Ap;
        As[acol + 0][arow] = a.x;
        As[acol + 1][arow] = a.y;
        As[acol + 2][arow] = a.z;
        As[acol + 3][arow] = a.w;
        *(float4*)&Bs[brow][bcol] = *(const float4*)Bp;
        __syncthreads();

        #pragma unroll
        for (int kk = 0; kk < 8; kk++) {
            float rm[8], rn[8];
            *(float4*)&rm[0] = *(const float4*)&As[kk][ty * 8];
            *(float4*)&rm[4] = *(const float4*)&As[kk][ty * 8 + 4];
            *(float4*)&rn[0] = *(const float4*)&Bs[kk][tx * 8];
            *(float4*)&rn[4] = *(const float4*)&Bs[kk][tx * 8 + 4];
            #pragma unroll
            for (int i = 0; i < 8; i++)
                #pragma unroll
                for (int j = 0; j < 8; j++)
                    acc[i][j] += rm[i] * rn[j];
        }
        __syncthreads();
        Ap += 8;
        Bp += 8 * DMODEL;
    }

    #pragma unroll
    for (int i = 0; i < 8; i++) {
        int m = bm + ty * 8 + i;
        #pragma unroll
        for (int jj = 0; jj < 8; jj += 4) {
            int n = bn + tx * 8 + jj;
            float4 bias = *(const float4*)&bo[n];
            float4 o;
            o.x = acc[i][jj + 0] + bias.x;
            o.y = acc[i][jj + 1] + bias.y;
            o.z = acc[i][jj + 2] + bias.z;
            o.w = acc[i][jj + 3] + bias.w;
            *(float4*)&out[m * DMODEL + n] = o;
        }
    }
}

// ---------------------------------------------------------------------------
// Launch
// ---------------------------------------------------------------------------
extern "C" void kernel_launch(void* const* d_in, const int* in_sizes, int n_in,
                              void* d_out, int out_size)
{
    (void)in_sizes; (void)n_in; (void)out_size;
    const float* x  = (const float*)d_in[0];
    const float* Wk = (const float*)d_in[1];
    const float* Wq = (const float*)d_in[2];
    const float* Wv = (const float*)d_in[3];
    const float* Wo = (const float*)d_in[4];
    const float* bo = (const float*)d_in[5];
    float* out = (float*)d_out;

    cudaFuncSetAttribute(attn_kernel,
                         cudaFuncAttributeMaxDynamicSharedMemorySize, ATTN_SMEM);

    dim3 g1(DMODEL / 128, MROWS / 128, 3);
    qkv_gemm<<<g1, 256>>>(x, Wq, Wk, Wv);

    dim3 g2(SEQ / QT, NBATCH * NH);
    attn_kernel<<<g2, 256, ATTN_SMEM>>>();

    dim3 g3(DMODEL / 128, MROWS / 128);
    out_gemm<<<g3, 256>>>(Wo, bo, out);
}

// round 3
// speedup vs baseline: 1.3559x; 1.3559x over previous
#include <cuda_runtime.h>
#include <cuda_bf16.h>
#include <cstdint>

// Problem constants
#define SEQ     2048
#define DMODEL  1024
#define NBATCH  2
#define NH      16
#define DH      64
#define MROWS   (NBATCH * SEQ)          // 4096

// ---------------------------------------------------------------------------
// Scratch (device globals: allocation-guard safe)
// ---------------------------------------------------------------------------
__device__ __align__(16) float g_q[MROWS * DMODEL];
__device__ __align__(16) float g_k[MROWS * DMODEL];
__device__ __align__(16) float g_v[MROWS * DMODEL];
__device__ __align__(16) float g_ctx[MROWS * DMODEL];

// bf16 split operands
__device__ __align__(16) __nv_bfloat16 g_xh[MROWS * DMODEL];
__device__ __align__(16) __nv_bfloat16 g_xl[MROWS * DMODEL];
__device__ __align__(16) __nv_bfloat16 g_ch[MROWS * DMODEL];
__device__ __align__(16) __nv_bfloat16 g_cl[MROWS * DMODEL];
// transposed weights [n][k], 0=Wq(pre-scaled by 0.125), 1=Wk, 2=Wv, 3=Wo
__device__ __align__(16) __nv_bfloat16 g_wh[4][DMODEL * DMODEL];
__device__ __align__(16) __nv_bfloat16 g_wl[4][DMODEL * DMODEL];

// ---------------------------------------------------------------------------
// PTX helpers (base-ISA only: mma.sync + cp.async; NO tcgen05 on this target)
// ---------------------------------------------------------------------------
__device__ __forceinline__ uint32_t s2u(const void* p) {
    uint32_t a;
    asm("{ .reg .u64 t; cvta.to.shared.u64 t, %1; cvt.u32.u64 %0, t; }"
        : "=r"(a) : "l"(p));
    return a;
}

__device__ __forceinline__ void mma_bf16(float* c, const uint32_t* a, const uint32_t* b) {
    asm volatile(
        "mma.sync.aligned.m16n8k16.row.col.f32.bf16.bf16.f32 "
        "{%0,%1,%2,%3}, {%4,%5,%6,%7}, {%8,%9}, {%0,%1,%2,%3};"
        : "+f"(c[0]), "+f"(c[1]), "+f"(c[2]), "+f"(c[3])
        : "r"(a[0]), "r"(a[1]), "r"(a[2]), "r"(a[3]), "r"(b[0]), "r"(b[1]));
}

__device__ __forceinline__ void cp16(uint32_t saddr, const void* g) {
    asm volatile("cp.async.cg.shared.global [%0], [%1], 16;"
                 :: "r"(saddr), "l"(g) : "memory");
}
#define CP_COMMIT() asm volatile("cp.async.commit_group;" ::: "memory")
#define CP_WAIT1()  asm volatile("cp.async.wait_group 1;" ::: "memory")
#define CP_WAIT0()  asm volatile("cp.async.wait_group 0;" ::: "memory")

// ---------------------------------------------------------------------------
// Conversion kernels (fp32 -> bf16 hi/lo split)
// ---------------------------------------------------------------------------
__global__ __launch_bounds__(256) void conv_x_k(const float* __restrict__ src)
{
    int i = (blockIdx.x * 256 + threadIdx.x) * 4;
    float4 v = *(const float4*)(src + i);
    float f[4] = {v.x, v.y, v.z, v.w};
    uint32_t h[4], l[4];
    #pragma unroll
    for (int j = 0; j < 4; j++) {
        __nv_bfloat16 hb = __float2bfloat16(f[j]);
        __nv_bfloat16 lb = __float2bfloat16(f[j] - __bfloat162float(hb));
        h[j] = __bfloat16_as_ushort(hb);
        l[j] = __bfloat16_as_ushort(lb);
    }
    *(uint2*)&g_xh[i] = make_uint2(h[0] | (h[1] << 16), h[2] | (h[3] << 16));
    *(uint2*)&g_xl[i] = make_uint2(l[0] | (l[1] << 16), l[2] | (l[3] << 16));
}

__global__ __launch_bounds__(256) void conv_ctx_k()
{
    int i = (blockIdx.x * 256 + threadIdx.x) * 4;
    float4 v = *(const float4*)(g_ctx + i);
    float f[4] = {v.x, v.y, v.z, v.w};
    uint32_t h[4], l[4];
    #pragma unroll
    for (int j = 0; j < 4; j++) {
        __nv_bfloat16 hb = __float2bfloat16(f[j]);
        __nv_bfloat16 lb = __float2bfloat16(f[j] - __bfloat162float(hb));
        h[j] = __bfloat16_as_ushort(hb);
        l[j] = __bfloat16_as_ushort(lb);
    }
    *(uint2*)&g_ch[i] = make_uint2(h[0] | (h[1] << 16), h[2] | (h[3] << 16));
    *(uint2*)&g_cl[i] = make_uint2(l[0] | (l[1] << 16), l[2] | (l[3] << 16));
}

// Transpose + split weights: Wt[n][k] = W[k][n]; Wq pre-scaled by 1/sqrt(DH)
__global__ __launch_bounds__(256) void conv_wt(
    const float* __restrict__ Wq, const float* __restrict__ Wk,
    const float* __restrict__ Wv, const float* __restrict__ Wo)
{
    __shared__ float t[32][33];
    int z = blockIdx.z;
    const float* W = (z == 0) ? Wq : (z == 1) ? Wk : (z == 2) ? Wv : Wo;
    float scale = (z == 0) ? 0.125f : 1.0f;
    int n0 = blockIdx.x * 32;
    int k0 = blockIdx.y * 32;
    #pragma unroll
    for (int jj = 0; jj < 32; jj += 8)
        t[threadIdx.y + jj][threadIdx.x] =
            W[(k0 + threadIdx.y + jj) * DMODEL + n0 + threadIdx.x] * scale;
    __syncthreads();
    __nv_bfloat16* Hh = g_wh[z];
    __nv_bfloat16* Hl = g_wl[z];
    #pragma unroll
    for (int jj = 0; jj < 32; jj += 8) {
        int n = n0 + threadIdx.y + jj;
        int k = k0 + threadIdx.x;
        float v = t[threadIdx.x][threadIdx.y + jj];
        __nv_bfloat16 hb = __float2bfloat16(v);
        __nv_bfloat16 lb = __float2bfloat16(v - __bfloat162float(hb));
        Hh[n * DMODEL + k] = hb;
        Hl[n * DMODEL + k] = lb;
    }
}

// ---------------------------------------------------------------------------
// mma.sync split-bf16 GEMM core.
// CTA tile 128x128, 8 warps (2m x 4n) of 64x32, K-chunk 32, double-buffered
// cp.async. SMEM row pitch LDA=40 halves (pad) -> conflict-free frag loads.
// Buffer layout: Ah | Al | Bh | Bl, each 128*40*2 = 10240 B. Buffer = 40960 B.
// ---------------------------------------------------------------------------
#define LDA        40
#define ARR_BYTES  (128 * LDA * 2)       // 10240
#define BUF_BYTES  (4 * ARR_BYTES)       // 40960
#define MMA_SMEM   (2 * BUF_BYTES)       // 81920

__device__ __forceinline__ void ld_chunk(
    uint32_t sb,
    const __nv_bfloat16* __restrict__ Ah, const __nv_bfloat16* __restrict__ Al,
    const __nv_bfloat16* __restrict__ Bh, const __nv_bfloat16* __restrict__ Bl,
    int bm, int bn, int k0, int tid)
{
    #pragma unroll
    for (int j = 0; j < 2; j++) {
        int op = tid + j * 256;
        int r  = op >> 2;
        int c8 = (op & 3) * 8;                 // half-index of 16B chunk
        uint32_t so = r * (LDA * 2) + c8 * 2;  // byte offset in array
        cp16(sb + so,                 Ah + (size_t)(bm + r) * DMODEL + k0 + c8);
        cp16(sb + ARR_BYTES + so,     Al + (size_t)(bm + r) * DMODEL + k0 + c8);
        cp16(sb + 2 * ARR_BYTES + so, Bh + (size_t)(bn + r) * DMODEL + k0 + c8);
        cp16(sb + 3 * ARR_BYTES + so, Bl + (size_t)(bn + r) * DMODEL + k0 + c8);
    }
}

__device__ __forceinline__ void compute_chunk(
    const char* buf, int wm, int wn, int g, int t, float acc[4][4][4])
{
    const __nv_bfloat16* As_h = (const __nv_bfloat16*)buf;
    const __nv_bfloat16* As_l = (const __nv_bfloat16*)(buf + ARR_BYTES);
    const __nv_bfloat16* Bs_h = (const __nv_bfloat16*)(buf + 2 * ARR_BYTES);
    const __nv_bfloat16* Bs_l = (const __nv_bfloat16*)(buf + 3 * ARR_BYTES);

    #pragma unroll
    for (int ks = 0; ks < 32; ks += 16) {
        const int c = ks + 2 * t;
        uint32_t ah[4][4], al[4][4], bh[4][2], bl[4][2];
        #pragma unroll
        for (int mi = 0; mi < 4; mi++) {
            int r0 = wm * 64 + mi * 16 + g;
            ah[mi][0] = *(const uint32_t*)&As_h[r0 * LDA + c];
            ah[mi][1] = *(const uint32_t*)&As_h[(r0 + 8) * LDA + c];
            ah[mi][2] = *(const uint32_t*)&As_h[r0 * LDA + c + 8];
            ah[mi][3] = *(const uint32_t*)&As_h[(r0 + 8) * LDA + c + 8];
            al[mi][0] = *(const uint32_t*)&As_l[r0 * LDA + c];
            al[mi][1] = *(const uint32_t*)&As_l[(r0 + 8) * LDA + c];
            al[mi][2] = *(const uint32_t*)&As_l[r0 * LDA + c + 8];
            al[mi][3] = *(const uint32_t*)&As_l[(r0 + 8) * LDA + c + 8];
        }
        #pragma unroll
        for (int ni = 0; ni < 4; ni++) {
            int rb = wn * 32 + ni * 8 + g;
            bh[ni][0] = *(const uint32_t*)&Bs_h[rb * LDA + c];
            bh[ni][1] = *(const uint32_t*)&Bs_h[rb * LDA + c + 8];
            bl[ni][0] = *(const uint32_t*)&Bs_l[rb * LDA + c];
            bl[ni][1] = *(const uint32_t*)&Bs_l[rb * LDA + c + 8];
        }
        #pragma unroll
        for (int mi = 0; mi < 4; mi++)
            #pragma unroll
            for (int ni = 0; ni < 4; ni++) {
                mma_bf16(acc[mi][ni], ah[mi], bh[ni]);
                mma_bf16(acc[mi][ni], ah[mi], bl[ni]);
                mma_bf16(acc[mi][ni], al[mi], bh[ni]);
            }
    }
}

// Full mainloop: fills acc for this CTA/warp.
__device__ __forceinline__ void gemm_mainloop(
    char* sm,
    const __nv_bfloat16* __restrict__ Ah, const __nv_bfloat16* __restrict__ Al,
    const __nv_bfloat16* __restrict__ Bh, const __nv_bfloat16* __restrict__ Bl,
    int bm, int bn, float acc[4][4][4])
{
    const int tid = threadIdx.x;
    const int wid = tid >> 5;
    const int lane = tid & 31;
    const int wm = wid >> 2;
    const int wn = wid & 3;
    const int g = lane >> 2;
    const int t = lane & 3;
    uint32_t smb = s2u(sm);

    #pragma unroll
    for (int mi = 0; mi < 4; mi++)
        #pragma unroll
        for (int ni = 0; ni < 4; ni++)
            #pragma unroll
            for (int j = 0; j < 4; j++)
                acc[mi][ni][j] = 0.0f;

    // prologue
    ld_chunk(smb, Ah, Al, Bh, Bl, bm, bn, 0, tid);
    CP_COMMIT();

    for (int ch = 0; ch < 32; ch++) {
        const char* cur = sm + (ch & 1) * BUF_BYTES;
        if (ch < 31) {
            __syncthreads();   // everyone done reading buf (ch+1)&1 (chunk ch-1)
            ld_chunk(smb + ((ch + 1) & 1) * BUF_BYTES, Ah, Al, Bh, Bl,
                     bm, bn, (ch + 1) * 32, tid);
            CP_COMMIT();
            CP_WAIT1();
        } else {
            CP_WAIT0();
        }
        __syncthreads();       // chunk ch data visible to all
        compute_chunk(cur, wm, wn, g, t, acc);
    }
}

// ---------------------------------------------------------------------------
// QKV projection (mma.sync). grid (8, 32, 3), block 256.
// z: 0 -> Q (Wq pre-scaled), 1 -> K, 2 -> V. Output layout [B*H, S, DH] fp32.
// ---------------------------------------------------------------------------
__global__ __launch_bounds__(256, 1) void qkv_mma()
{
    extern __shared__ char sm[];
    const int z  = blockIdx.z;
    const int bm = blockIdx.y * 128;
    const int bn = blockIdx.x * 128;
    float* Out = (z == 0) ? g_q : (z == 1) ? g_k : g_v;

    float acc[4][4][4];
    gemm_mainloop(sm, g_xh, g_xl, g_wh[z], g_wl[z], bm, bn, acc);

    const int tid = threadIdx.x;
    const int wid = tid >> 5;
    const int lane = tid & 31;
    const int wm = wid >> 2, wn = wid & 3;
    const int g = lane >> 2, t = lane & 3;

    #pragma unroll
    for (int mi = 0; mi < 4; mi++) {
        int row = bm + wm * 64 + mi * 16 + g;
        int b = row >> 11;
        int s = row & (SEQ - 1);
        #pragma unroll
        for (int ni = 0; ni < 4; ni++) {
            int col = bn + wn * 32 + ni * 8 + 2 * t;
            int h = col >> 6;
            int d = col & (DH - 1);
            size_t base = (((size_t)(b * NH + h)) * SEQ) * DH + d;
            *(float2*)&Out[base + (size_t)s * DH] =
                make_float2(acc[mi][ni][0], acc[mi][ni][1]);
            *(float2*)&Out[base + (size_t)(s + 8) * DH] =
                make_float2(acc[mi][ni][2], acc[mi][ni][3]);
        }
    }
}

// ---------------------------------------------------------------------------
// Output projection + bias (mma.sync). grid (8, 32), block 256.
// ---------------------------------------------------------------------------
__global__ __launch_bounds__(256, 1) void out_mma(const float* __restrict__ bo,
                                                  float* __restrict__ out)
{
    extern __shared__ char sm[];
    const int bm = blockIdx.y * 128;
    const int bn = blockIdx.x * 128;

    float acc[4][4][4];
    gemm_mainloop(sm, g_ch, g_cl, g_wh[3], g_wl[3], bm, bn, acc);

    const int tid = threadIdx.x;
    const int wid = tid >> 5;
    const int lane = tid & 31;
    const int wm = wid >> 2, wn = wid & 3;
    const int g = lane >> 2, t = lane & 3;

    #pragma unroll
    for (int mi = 0; mi < 4; mi++) {
        int row = bm + wm * 64 + mi * 16 + g;
        #pragma unroll
        for (int ni = 0; ni < 4; ni++) {
            int col = bn + wn * 32 + ni * 8 + 2 * t;
            float2 bias = *(const float2*)&bo[col];
            *(float2*)&out[(size_t)row * DMODEL + col] =
                make_float2(acc[mi][ni][0] + bias.x, acc[mi][ni][1] + bias.y);
            *(float2*)&out[(size_t)(row + 8) * DMODEL + col] =
                make_float2(acc[mi][ni][2] + bias.x, acc[mi][ni][3] + bias.y);
        }
    }
}

// ---------------------------------------------------------------------------
// Flash-style attention (fp32 SIMT, NO mask — matches reference). Unchanged.
// ---------------------------------------------------------------------------
#define QT 128
#define KT 64
#define QSP 132
#define KSP 68
#define ATTN_SMEM ((DH*QSP + DH*KSP + QT*KT + KT*DH) * 4)

__global__ __launch_bounds__(256, 2) void attn_kernel()
{
    extern __shared__ float smf[];
    float* Qs = smf;
    float* Ks = Qs + DH * QSP;
    float* Ps = Ks + DH * KSP;
    float* Vs = Ps + QT * KT;

    const int bh = blockIdx.y;
    const int q0 = blockIdx.x * QT;
    const float* Qb = g_q + bh * (SEQ * DH);
    const float* Kb = g_k + bh * (SEQ * DH);
    const float* Vb = g_v + bh * (SEQ * DH);

    const int tid = threadIdx.x;
    const int tx = tid & 15;
    const int ty = tid >> 4;

    #pragma unroll
    for (int i = 0; i < 8; i++) {
        int idx4 = tid + i * 256;
        int r  = idx4 >> 4;
        int d0 = (idx4 & 15) << 2;
        float4 v = *(const float4*)(Qb + (q0 + r) * DH + d0);
        Qs[(d0 + 0) * QSP + r] = v.x;
        Qs[(d0 + 1) * QSP + r] = v.y;
        Qs[(d0 + 2) * QSP + r] = v.z;
        Qs[(d0 + 3) * QSP + r] = v.w;
    }

    float m_run[8], l_run[8], acc[8][4];
    #pragma unroll
    for (int a = 0; a < 8; a++) {
        m_run[a] = -1e30f;
        l_run[a] = 0.0f;
        acc[a][0] = acc[a][1] = acc[a][2] = acc[a][3] = 0.0f;
    }

    for (int k0 = 0; k0 < SEQ; k0 += KT) {
        __syncthreads();

        #pragma unroll
        for (int i = 0; i < 4; i++) {
            int idx4 = tid + i * 256;
            int r  = idx4 >> 4;
            int d0 = (idx4 & 15) << 2;
            float4 kv = *(const float4*)(Kb + (k0 + r) * DH + d0);
            Ks[(d0 + 0) * KSP + r] = kv.x;
            Ks[(d0 + 1) * KSP + r] = kv.y;
            Ks[(d0 + 2) * KSP + r] = kv.z;
            Ks[(d0 + 3) * KSP + r] = kv.w;
            *(float4*)&Vs[r * DH + d0] = *(const float4*)(Vb + (k0 + r) * DH + d0);
        }
        __syncthreads();

        float s[8][4];
        #pragma unroll
        for (int a = 0; a < 8; a++)
            s[a][0] = s[a][1] = s[a][2] = s[a][3] = 0.0f;

        #pragma unroll 8
        for (int d = 0; d < DH; d++) {
            float rq[8], rk[4];
            *(float4*)&rq[0] = *(const float4*)&Qs[d * QSP + ty * 8];
            *(float4*)&rq[4] = *(const float4*)&Qs[d * QSP + ty * 8 + 4];
            *(float4*)&rk[0] = *(const float4*)&Ks[d * KSP + tx * 4];
            #pragma unroll
            for (int a = 0; a < 8; a++)
                #pragma unroll
                for (int j = 0; j < 4; j++)
                    s[a][j] += rq[a] * rk[j];
        }

        #pragma unroll
        for (int a = 0; a < 8; a++) {
            float mt = fmaxf(fmaxf(s[a][0], s[a][1]), fmaxf(s[a][2], s[a][3]));
            #pragma unroll
            for (int o = 8; o > 0; o >>= 1)
                mt = fmaxf(mt, __shfl_xor_sync(0xffffffffu, mt, o));
            float mn = fmaxf(m_run[a], mt);
            float f  = __expf(m_run[a] - mn);
            float ssum = 0.0f;
            #pragma unroll
            for (int j = 0; j < 4; j++) {
                float p = __expf(s[a][j] - mn);
                s[a][j] = p;
                ssum += p;
            }
            #pragma unroll
            for (int o = 8; o > 0; o >>= 1)
                ssum += __shfl_xor_sync(0xffffffffu, ssum, o);
            l_run[a] = l_run[a] * f + ssum;
            m_run[a] = mn;
            acc[a][0] *= f; acc[a][1] *= f; acc[a][2] *= f; acc[a][3] *= f;
        }

        #pragma unroll
        for (int a = 0; a < 8; a++) {
            float4 p4 = make_float4(s[a][0], s[a][1], s[a][2], s[a][3]);
            *(float4*)&Ps[(ty * 8 + a) * KT + tx * 4] = p4;
        }
        __syncthreads();

        #pragma unroll 4
        for (int c0 = 0; c0 < KT; c0 += 4) {
            float4 v0 = *(const float4*)&Vs[(c0 + 0) * DH + tx * 4];
            float4 v1 = *(const float4*)&Vs[(c0 + 1) * DH + tx * 4];
            float4 v2 = *(const float4*)&Vs[(c0 + 2) * DH + tx * 4];
            float4 v3 = *(const float4*)&Vs[(c0 + 3) * DH + tx * 4];
            #pragma unroll
            for (int a = 0; a < 8; a++) {
                float4 p = *(const float4*)&Ps[(ty * 8 + a) * KT + c0];
                acc[a][0] += p.x * v0.x + p.y * v1.x + p.z * v2.x + p.w * v3.x;
                acc[a][1] += p.x * v0.y + p.y * v1.y + p.z * v2.y + p.w * v3.y;
                acc[a][2] += p.x * v0.z + p.y * v1.z + p.z * v2.z + p.w * v3.z;
                acc[a][3] += p.x * v0.w + p.y * v1.w + p.z * v2.w + p.w * v3.w;
            }
        }
    }

    const int b = bh >> 4;
    const int h = bh & 15;
    #pragma unroll
    for (int a = 0; a < 8; a++) {
        int r = q0 + ty * 8 + a;
        float inv = 1.0f / l_run[a];
        float4 o;
        o.x = acc[a][0] * inv;
        o.y = acc[a][1] * inv;
        o.z = acc[a][2] * inv;
        o.w = acc[a][3] * inv;
        *(float4*)&g_ctx[(b * SEQ + r) * DMODEL + h * DH + tx * 4] = o;
    }
}

// ---------------------------------------------------------------------------
// Launch
// ---------------------------------------------------------------------------
extern "C" void kernel_launch(void* const* d_in, const int* in_sizes, int n_in,
                              void* d_out, int out_size)
{
    (void)in_sizes; (void)n_in; (void)out_size;
    const float* x  = (const float*)d_in[0];
    const float* Wk = (const float*)d_in[1];
    const float* Wq = (const float*)d_in[2];
    const float* Wv = (const float*)d_in[3];
    const float* Wo = (const float*)d_in[4];
    const float* bo = (const float*)d_in[5];
    float* out = (float*)d_out;

    cudaFuncSetAttribute(qkv_mma, cudaFuncAttributeMaxDynamicSharedMemorySize, MMA_SMEM);
    cudaFuncSetAttribute(out_mma, cudaFuncAttributeMaxDynamicSharedMemorySize, MMA_SMEM);
    cudaFuncSetAttribute(attn_kernel, cudaFuncAttributeMaxDynamicSharedMemorySize, ATTN_SMEM);

    // 1. weight transpose + split, input split
    conv_wt<<<dim3(32, 32, 4), dim3(32, 8)>>>(Wq, Wk, Wv, Wo);
    conv_x_k<<<(MROWS * DMODEL / 4) / 256, 256>>>(x);

    // 2. QKV projections (mma.sync tensor cores)
    qkv_mma<<<dim3(DMODEL / 128, MROWS / 128, 3), 256, MMA_SMEM>>>();

    // 3. attention (SIMT fp32)
    attn_kernel<<<dim3(SEQ / QT, NBATCH * NH), 256, ATTN_SMEM>>>();

    // 4. ctx split + output projection (mma.sync tensor cores)
    conv_ctx_k<<<(MROWS * DMODEL / 4) / 256, 256>>>();
    out_mma<<<dim3(DMODEL / 128, MROWS / 128), 256, MMA_SMEM>>>(bo, out);
}

// round 4
// speedup vs baseline: 2.1899x; 1.6151x over previous
#include <cuda_runtime.h>
#include <cuda_bf16.h>
#include <cstdint>

// Problem constants
#define SEQ     2048
#define DMODEL  1024
#define NBATCH  2
#define NH      16
#define DH      64
#define MROWS   (NBATCH * SEQ)          // 4096

// ---------------------------------------------------------------------------
// Scratch (device globals: allocation-guard safe)
// ---------------------------------------------------------------------------
// bf16 split operands
__device__ __align__(16) __nv_bfloat16 g_xh[MROWS * DMODEL];
__device__ __align__(16) __nv_bfloat16 g_xl[MROWS * DMODEL];
__device__ __align__(16) __nv_bfloat16 g_ch[MROWS * DMODEL];
__device__ __align__(16) __nv_bfloat16 g_cl[MROWS * DMODEL];
// Q,K: [B*H][S][DH]; V: transposed [B*H][DH][S]
__device__ __align__(16) __nv_bfloat16 g_qh[MROWS * DMODEL];
__device__ __align__(16) __nv_bfloat16 g_ql[MROWS * DMODEL];
__device__ __align__(16) __nv_bfloat16 g_kh[MROWS * DMODEL];
__device__ __align__(16) __nv_bfloat16 g_kl[MROWS * DMODEL];
__device__ __align__(16) __nv_bfloat16 g_vh[MROWS * DMODEL];
__device__ __align__(16) __nv_bfloat16 g_vl[MROWS * DMODEL];
// transposed weights [n][k], 0=Wq(pre-scaled by 0.125), 1=Wk, 2=Wv, 3=Wo
__device__ __align__(16) __nv_bfloat16 g_wh[4][DMODEL * DMODEL];
__device__ __align__(16) __nv_bfloat16 g_wl[4][DMODEL * DMODEL];

// ---------------------------------------------------------------------------
// PTX helpers (base-ISA only: mma.sync + cp.async)
// ---------------------------------------------------------------------------
__device__ __forceinline__ uint32_t s2u(const void* p) {
    uint32_t a;
    asm("{ .reg .u64 t; cvta.to.shared.u64 t, %1; cvt.u32.u64 %0, t; }"
        : "=r"(a) : "l"(p));
    return a;
}

__device__ __forceinline__ void mma_bf16(float* c, const uint32_t* a, const uint32_t* b) {
    asm volatile(
        "mma.sync.aligned.m16n8k16.row.col.f32.bf16.bf16.f32 "
        "{%0,%1,%2,%3}, {%4,%5,%6,%7}, {%8,%9}, {%0,%1,%2,%3};"
        : "+f"(c[0]), "+f"(c[1]), "+f"(c[2]), "+f"(c[3])
        : "r"(a[0]), "r"(a[1]), "r"(a[2]), "r"(a[3]), "r"(b[0]), "r"(b[1]));
}

__device__ __forceinline__ void cp16(uint32_t saddr, const void* g) {
    asm volatile("cp.async.cg.shared.global [%0], [%1], 16;"
                 :: "r"(saddr), "l"(g) : "memory");
}
#define CP_COMMIT() asm volatile("cp.async.commit_group;" ::: "memory")
#define CP_WAIT1()  asm volatile("cp.async.wait_group 1;" ::: "memory")
#define CP_WAIT0()  asm volatile("cp.async.wait_group 0;" ::: "memory")

__device__ __forceinline__ void split_pack(float x, float y, uint32_t& hi, uint32_t& lo) {
    __nv_bfloat16 hx = __float2bfloat16(x);
    __nv_bfloat16 hy = __float2bfloat16(y);
    __nv_bfloat16 lx = __float2bfloat16(x - __bfloat162float(hx));
    __nv_bfloat16 ly = __float2bfloat16(y - __bfloat162float(hy));
    hi = (uint32_t)__bfloat16_as_ushort(hx) | ((uint32_t)__bfloat16_as_ushort(hy) << 16);
    lo = (uint32_t)__bfloat16_as_ushort(lx) | ((uint32_t)__bfloat16_as_ushort(ly) << 16);
}

// ---------------------------------------------------------------------------
// Conversion kernels
// ---------------------------------------------------------------------------
__global__ __launch_bounds__(256) void conv_x_k(const float* __restrict__ src)
{
    int i = (blockIdx.x * 256 + threadIdx.x) * 4;
    float4 v = *(const float4*)(src + i);
    float f[4] = {v.x, v.y, v.z, v.w};
    uint32_t h[4], l[4];
    #pragma unroll
    for (int j = 0; j < 4; j++) {
        __nv_bfloat16 hb = __float2bfloat16(f[j]);
        __nv_bfloat16 lb = __float2bfloat16(f[j] - __bfloat162float(hb));
        h[j] = __bfloat16_as_ushort(hb);
        l[j] = __bfloat16_as_ushort(lb);
    }
    *(uint2*)&g_xh[i] = make_uint2(h[0] | (h[1] << 16), h[2] | (h[3] << 16));
    *(uint2*)&g_xl[i] = make_uint2(l[0] | (l[1] << 16), l[2] | (l[3] << 16));
}

__global__ __launch_bounds__(256) void conv_wt(
    const float* __restrict__ Wq, const float* __restrict__ Wk,
    const float* __restrict__ Wv, const float* __restrict__ Wo)
{
    __shared__ float t[32][33];
    int z = blockIdx.z;
    const float* W = (z == 0) ? Wq : (z == 1) ? Wk : (z == 2) ? Wv : Wo;
    float scale = (z == 0) ? 0.125f : 1.0f;
    int n0 = blockIdx.x * 32;
    int k0 = blockIdx.y * 32;
    #pragma unroll
    for (int jj = 0; jj < 32; jj += 8)
        t[threadIdx.y + jj][threadIdx.x] =
            W[(k0 + threadIdx.y + jj) * DMODEL + n0 + threadIdx.x] * scale;
    __syncthreads();
    __nv_bfloat16* Hh = g_wh[z];
    __nv_bfloat16* Hl = g_wl[z];
    #pragma unroll
    for (int jj = 0; jj < 32; jj += 8) {
        int n = n0 + threadIdx.y + jj;
        int k = k0 + threadIdx.x;
        float v = t[threadIdx.x][threadIdx.y + jj];
        __nv_bfloat16 hb = __float2bfloat16(v);
        __nv_bfloat16 lb = __float2bfloat16(v - __bfloat162float(hb));
        Hh[n * DMODEL + k] = hb;
        Hl[n * DMODEL + k] = lb;
    }
}

// ---------------------------------------------------------------------------
// mma.sync split-bf16 GEMM core (unchanged from round 3)
// ---------------------------------------------------------------------------
#define LDA        40
#define ARR_BYTES  (128 * LDA * 2)       // 10240
#define BUF_BYTES  (4 * ARR_BYTES)       // 40960
#define MMA_SMEM   (2 * BUF_BYTES)       // 81920

__device__ __forceinline__ void ld_chunk(
    uint32_t sb,
    const __nv_bfloat16* __restrict__ Ah, const __nv_bfloat16* __restrict__ Al,
    const __nv_bfloat16* __restrict__ Bh, const __nv_bfloat16* __restrict__ Bl,
    int bm, int bn, int k0, int tid)
{
    #pragma unroll
    for (int j = 0; j < 2; j++) {
        int op = tid + j * 256;
        int r  = op >> 2;
        int c8 = (op & 3) * 8;
        uint32_t so = r * (LDA * 2) + c8 * 2;
        cp16(sb + so,                 Ah + (size_t)(bm + r) * DMODEL + k0 + c8);
        cp16(sb + ARR_BYTES + so,     Al + (size_t)(bm + r) * DMODEL + k0 + c8);
        cp16(sb + 2 * ARR_BYTES + so, Bh + (size_t)(bn + r) * DMODEL + k0 + c8);
        cp16(sb + 3 * ARR_BYTES + so, Bl + (size_t)(bn + r) * DMODEL + k0 + c8);
    }
}

__device__ __forceinline__ void compute_chunk(
    const char* buf, int wm, int wn, int g, int t, float acc[4][4][4])
{
    const __nv_bfloat16* As_h = (const __nv_bfloat16*)buf;
    const __nv_bfloat16* As_l = (const __nv_bfloat16*)(buf + ARR_BYTES);
    const __nv_bfloat16* Bs_h = (const __nv_bfloat16*)(buf + 2 * ARR_BYTES);
    const __nv_bfloat16* Bs_l = (const __nv_bfloat16*)(buf + 3 * ARR_BYTES);

    #pragma unroll
    for (int ks = 0; ks < 32; ks += 16) {
        const int c = ks + 2 * t;
        uint32_t ah[4][4], al[4][4], bh[4][2], bl[4][2];
        #pragma unroll
        for (int mi = 0; mi < 4; mi++) {
            int r0 = wm * 64 + mi * 16 + g;
            ah[mi][0] = *(const uint32_t*)&As_h[r0 * LDA + c];
            ah[mi][1] = *(const uint32_t*)&As_h[(r0 + 8) * LDA + c];
            ah[mi][2] = *(const uint32_t*)&As_h[r0 * LDA + c + 8];
            ah[mi][3] = *(const uint32_t*)&As_h[(r0 + 8) * LDA + c + 8];
            al[mi][0] = *(const uint32_t*)&As_l[r0 * LDA + c];
            al[mi][1] = *(const uint32_t*)&As_l[(r0 + 8) * LDA + c];
            al[mi][2] = *(const uint32_t*)&As_l[r0 * LDA + c + 8];
            al[mi][3] = *(const uint32_t*)&As_l[(r0 + 8) * LDA + c + 8];
        }
        #pragma unroll
        for (int ni = 0; ni < 4; ni++) {
            int rb = wn * 32 + ni * 8 + g;
            bh[ni][0] = *(const uint32_t*)&Bs_h[rb * LDA + c];
            bh[ni][1] = *(const uint32_t*)&Bs_h[rb * LDA + c + 8];
            bl[ni][0] = *(const uint32_t*)&Bs_l[rb * LDA + c];
            bl[ni][1] = *(const uint32_t*)&Bs_l[rb * LDA + c + 8];
        }
        #pragma unroll
        for (int mi = 0; mi < 4; mi++)
            #pragma unroll
            for (int ni = 0; ni < 4; ni++) {
                mma_bf16(acc[mi][ni], ah[mi], bh[ni]);
                mma_bf16(acc[mi][ni], ah[mi], bl[ni]);
                mma_bf16(acc[mi][ni], al[mi], bh[ni]);
            }
    }
}

__device__ __forceinline__ void gemm_mainloop(
    char* sm,
    const __nv_bfloat16* __restrict__ Ah, const __nv_bfloat16* __restrict__ Al,
    const __nv_bfloat16* __restrict__ Bh, const __nv_bfloat16* __restrict__ Bl,
    int bm, int bn, float acc[4][4][4])
{
    const int tid = threadIdx.x;
    const int wid = tid >> 5;
    const int lane = tid & 31;
    const int wm = wid >> 2;
    const int wn = wid & 3;
    const int g = lane >> 2;
    const int t = lane & 3;
    uint32_t smb = s2u(sm);

    #pragma unroll
    for (int mi = 0; mi < 4; mi++)
        #pragma unroll
        for (int ni = 0; ni < 4; ni++)
            #pragma unroll
            for (int j = 0; j < 4; j++)
                acc[mi][ni][j] = 0.0f;

    ld_chunk(smb, Ah, Al, Bh, Bl, bm, bn, 0, tid);
    CP_COMMIT();

    for (int ch = 0; ch < 32; ch++) {
        const char* cur = sm + (ch & 1) * BUF_BYTES;
        if (ch < 31) {
            __syncthreads();
            ld_chunk(smb + ((ch + 1) & 1) * BUF_BYTES, Ah, Al, Bh, Bl,
                     bm, bn, (ch + 1) * 32, tid);
            CP_COMMIT();
            CP_WAIT1();
        } else {
            CP_WAIT0();
        }
        __syncthreads();
        compute_chunk(cur, wm, wn, g, t, acc);
    }
}

// ---------------------------------------------------------------------------
// QKV projection (mma.sync). grid (8, 32, 3), block 256.
// Outputs bf16 hi/lo: Q,K -> [B*H][S][DH]; V -> transposed [B*H][DH][S].
// ---------------------------------------------------------------------------
__global__ __launch_bounds__(256, 1) void qkv_mma()
{
    extern __shared__ char sm[];
    const int z  = blockIdx.z;
    const int bm = blockIdx.y * 128;
    const int bn = blockIdx.x * 128;

    float acc[4][4][4];
    gemm_mainloop(sm, g_xh, g_xl, g_wh[z], g_wl[z], bm, bn, acc);

    const int tid = threadIdx.x;
    const int wid = tid >> 5;
    const int lane = tid & 31;
    const int wm = wid >> 2, wn = wid & 3;
    const int g = lane >> 2, t = lane & 3;

    if (z < 2) {
        __nv_bfloat16* Oh = (z == 0) ? g_qh : g_kh;
        __nv_bfloat16* Ol = (z == 0) ? g_ql : g_kl;
        #pragma unroll
        for (int mi = 0; mi < 4; mi++) {
            int row = bm + wm * 64 + mi * 16 + g;
            int b = row >> 11;
            int s = row & (SEQ - 1);
            #pragma unroll
            for (int ni = 0; ni < 4; ni++) {
                int col = bn + wn * 32 + ni * 8 + 2 * t;
                int h = col >> 6;
                int d = col & (DH - 1);
                size_t base = ((size_t)(b * NH + h) * SEQ + s) * DH + d;
                uint32_t ph, pl;
                split_pack(acc[mi][ni][0], acc[mi][ni][1], ph, pl);
                *(uint32_t*)&Oh[base] = ph;
                *(uint32_t*)&Ol[base] = pl;
                split_pack(acc[mi][ni][2], acc[mi][ni][3], ph, pl);
                *(uint32_t*)&Oh[base + 8 * DH] = ph;
                *(uint32_t*)&Ol[base + 8 * DH] = pl;
            }
        }
    } else {
        // V: stage fp32 tile in SMEM, write transposed [B*H][DH][S]
        float* smf = (float*)sm;                    // [128][133]
        __syncthreads();
        #pragma unroll
        for (int mi = 0; mi < 4; mi++) {
            int r0 = wm * 64 + mi * 16 + g;
            #pragma unroll
            for (int ni = 0; ni < 4; ni++) {
                int c0 = wn * 32 + ni * 8 + 2 * t;
                smf[r0 * 133 + c0]           = acc[mi][ni][0];
                smf[r0 * 133 + c0 + 1]       = acc[mi][ni][1];
                smf[(r0 + 8) * 133 + c0]     = acc[mi][ni][2];
                smf[(r0 + 8) * 133 + c0 + 1] = acc[mi][ni][3];
            }
        }
        __syncthreads();
        int b = bm >> 11;
        int s_base = bm & (SEQ - 1);
        #pragma unroll
        for (int dr = 0; dr < 16; dr++) {
            int d_loc = wid * 16 + dr;
            int gcol = bn + d_loc;
            int h = gcol >> 6;
            int dd = gcol & (DH - 1);
            size_t base = ((size_t)(b * NH + h) * DH + dd) * SEQ + s_base;
            #pragma unroll
            for (int rep = 0; rep < 2; rep++) {
                int idx = lane + rep * 32;          // u32 index; s = 2*idx
                float f0 = smf[(2 * idx) * 133 + d_loc];
                float f1 = smf[(2 * idx + 1) * 133 + d_loc];
                uint32_t ph, pl;
                split_pack(f0, f1, ph, pl);
                *(uint32_t*)&g_vh[base + 2 * idx] = ph;
                *(uint32_t*)&g_vl[base + 2 * idx] = pl;
            }
        }
    }
}

// ---------------------------------------------------------------------------
// Output projection + bias (mma.sync). grid (8, 32), block 256.
// ---------------------------------------------------------------------------
__global__ __launch_bounds__(256, 1) void out_mma(const float* __restrict__ bo,
                                                  float* __restrict__ out)
{
    extern __shared__ char sm[];
    const int bm = blockIdx.y * 128;
    const int bn = blockIdx.x * 128;

    float acc[4][4][4];
    gemm_mainloop(sm, g_ch, g_cl, g_wh[3], g_wl[3], bm, bn, acc);

    const int tid = threadIdx.x;
    const int wid = tid >> 5;
    const int lane = tid & 31;
    const int wm = wid >> 2, wn = wid & 3;
    const int g = lane >> 2, t = lane & 3;

    #pragma unroll
    for (int mi = 0; mi < 4; mi++) {
        int row = bm + wm * 64 + mi * 16 + g;
        #pragma unroll
        for (int ni = 0; ni < 4; ni++) {
            int col = bn + wn * 32 + ni * 8 + 2 * t;
            float2 bias = *(const float2*)&bo[col];
            *(float2*)&out[(size_t)row * DMODEL + col] =
                make_float2(acc[mi][ni][0] + bias.x, acc[mi][ni][1] + bias.y);
            *(float2*)&out[(size_t)(row + 8) * DMODEL + col] =
                make_float2(acc[mi][ni][2] + bias.x, acc[mi][ni][3] + bias.y);
        }
    }
}

// ---------------------------------------------------------------------------
// Attention on mma.sync (split bf16, 3-pass QK^T and PV). NO mask.
// grid (16, 32), block 256 (8 warps, 2x4). Q-tile 128, K-tile 128.
// SMEM: Qh|Ql [128][72], Kh|Kl [128][72], Vth|Vtl [64][136], Ph|Pl [128][136]
// ---------------------------------------------------------------------------
#define QP 72
#define VP 136
#define PP 136
#define OFF_Q  0
#define OFF_K  36864
#define OFF_V  73728
#define OFF_P  108544
#define ATTN_SMEM 178176

__device__ __forceinline__ void attn_ld_K(uint32_t smb, size_t qkb, int k0, int tid)
{
    #pragma unroll
    for (int j = 0; j < 8; j++) {
        int c = tid + j * 256;
        int comp = c >> 10;
        int cc = c & 1023;
        int r = cc >> 3, c8 = (cc & 7) * 8;
        const __nv_bfloat16* src = (comp ? g_kl : g_kh) + qkb + (size_t)(k0 + r) * DH + c8;
        cp16(smb + OFF_K + comp * 18432 + (r * QP + c8) * 2, src);
    }
}

__device__ __forceinline__ void attn_ld_V(uint32_t smb, size_t qkb, int k0, int tid)
{
    #pragma unroll
    for (int j = 0; j < 8; j++) {
        int c = tid + j * 256;
        int comp = c >> 10;
        int cc = c & 1023;
        int r = cc >> 4, c8 = (cc & 15) * 8;
        const __nv_bfloat16* src = (comp ? g_vl : g_vh) + qkb + (size_t)r * SEQ + k0 + c8;
        cp16(smb + OFF_V + comp * 17408 + (r * VP + c8) * 2, src);
    }
}

__global__ __launch_bounds__(256, 1) void attn_mma()
{
    extern __shared__ char sm[];
    __shared__ float sM[128][4];
    __shared__ float sL[128][4];

    const __nv_bfloat16* Qh = (const __nv_bfloat16*)(sm + OFF_Q);
    const __nv_bfloat16* Ql = Qh + 128 * QP;
    const __nv_bfloat16* Kh = (const __nv_bfloat16*)(sm + OFF_K);
    const __nv_bfloat16* Kl = Kh + 128 * QP;
    const __nv_bfloat16* Vth = (const __nv_bfloat16*)(sm + OFF_V);
    const __nv_bfloat16* Vtl = Vth + 64 * VP;
    __nv_bfloat16* Ph = (__nv_bfloat16*)(sm + OFF_P);
    __nv_bfloat16* Pl = Ph + 128 * PP;

    const int bh = blockIdx.y;
    const int q0 = blockIdx.x * 128;
    const int tid = threadIdx.x;
    const int wid = tid >> 5, lane = tid & 31;
    const int wm = wid >> 2, wn = wid & 3;
    const int g = lane >> 2, t = lane & 3;
    const size_t qkb = (size_t)bh * SEQ * DH;
    uint32_t smb = s2u(sm);

    // prologue: Q tile + iter-0 K/V
    #pragma unroll
    for (int j = 0; j < 8; j++) {
        int c = tid + j * 256;
        int comp = c >> 10;
        int cc = c & 1023;
        int r = cc >> 3, c8 = (cc & 7) * 8;
        const __nv_bfloat16* src = (comp ? g_ql : g_qh) + qkb + (size_t)(q0 + r) * DH + c8;
        cp16(smb + OFF_Q + comp * 18432 + (r * QP + c8) * 2, src);
    }
    attn_ld_K(smb, qkb, 0, tid);
    attn_ld_V(smb, qkb, 0, tid);
    CP_COMMIT();

    float m_run[8], l_run[8], cacc[4][2][4];
    #pragma unroll
    for (int i = 0; i < 8; i++) { m_run[i] = -1e30f; l_run[i] = 0.0f; }
    #pragma unroll
    for (int mi = 0; mi < 4; mi++)
        #pragma unroll
        for (int ni = 0; ni < 2; ni++)
            #pragma unroll
            for (int j = 0; j < 4; j++) cacc[mi][ni][j] = 0.0f;

    for (int it = 0; it < SEQ / 128; it++) {
        CP_WAIT0();
        __syncthreads();

        // ---- S = Q @ K^T (3-pass) ----
        float sacc[4][4][4];
        #pragma unroll
        for (int mi = 0; mi < 4; mi++)
            #pragma unroll
            for (int ni = 0; ni < 4; ni++)
                #pragma unroll
                for (int j = 0; j < 4; j++) sacc[mi][ni][j] = 0.0f;

        #pragma unroll
        for (int ks = 0; ks < 4; ks++) {
            const int c = ks * 16 + 2 * t;
            uint32_t qa_h[4][4], qa_l[4][4], kb_h[4][2], kb_l[4][2];
            #pragma unroll
            for (int mi = 0; mi < 4; mi++) {
                int r0 = wm * 64 + mi * 16 + g;
                qa_h[mi][0] = *(const uint32_t*)&Qh[r0 * QP + c];
                qa_h[mi][1] = *(const uint32_t*)&Qh[(r0 + 8) * QP + c];
                qa_h[mi][2] = *(const uint32_t*)&Qh[r0 * QP + c + 8];
                qa_h[mi][3] = *(const uint32_t*)&Qh[(r0 + 8) * QP + c + 8];
                qa_l[mi][0] = *(const uint32_t*)&Ql[r0 * QP + c];
                qa_l[mi][1] = *(const uint32_t*)&Ql[(r0 + 8) * QP + c];
                qa_l[mi][2] = *(const uint32_t*)&Ql[r0 * QP + c + 8];
                qa_l[mi][3] = *(const uint32_t*)&Ql[(r0 + 8) * QP + c + 8];
            }
            #pragma unroll
            for (int ni = 0; ni < 4; ni++) {
                int rb = wn * 32 + ni * 8 + g;
                kb_h[ni][0] = *(const uint32_t*)&Kh[rb * QP + c];
                kb_h[ni][1] = *(const uint32_t*)&Kh[rb * QP + c + 8];
                kb_l[ni][0] = *(const uint32_t*)&Kl[rb * QP + c];
                kb_l[ni][1] = *(const uint32_t*)&Kl[rb * QP + c + 8];
            }
            #pragma unroll
            for (int mi = 0; mi < 4; mi++)
                #pragma unroll
                for (int ni = 0; ni < 4; ni++) {
                    mma_bf16(sacc[mi][ni], qa_h[mi], kb_h[ni]);
                    mma_bf16(sacc[mi][ni], qa_h[mi], kb_l[ni]);
                    mma_bf16(sacc[mi][ni], qa_l[mi], kb_h[ni]);
                }
        }

        // ---- online softmax (cross-warp row stats via sM/sL) ----
        float lm[8];
        #pragma unroll
        for (int i = 0; i < 8; i++) lm[i] = -1e30f;
        #pragma unroll
        for (int mi = 0; mi < 4; mi++)
            #pragma unroll
            for (int ni = 0; ni < 4; ni++) {
                lm[mi * 2]     = fmaxf(lm[mi * 2],     fmaxf(sacc[mi][ni][0], sacc[mi][ni][1]));
                lm[mi * 2 + 1] = fmaxf(lm[mi * 2 + 1], fmaxf(sacc[mi][ni][2], sacc[mi][ni][3]));
            }
        #pragma unroll
        for (int i = 0; i < 8; i++) {
            lm[i] = fmaxf(lm[i], __shfl_xor_sync(0xffffffffu, lm[i], 1));
            lm[i] = fmaxf(lm[i], __shfl_xor_sync(0xffffffffu, lm[i], 2));
        }
        if (t == 0) {
            #pragma unroll
            for (int mi = 0; mi < 4; mi++) {
                sM[wm * 64 + mi * 16 + g][wn]     = lm[mi * 2];
                sM[wm * 64 + mi * 16 + 8 + g][wn] = lm[mi * 2 + 1];
            }
        }
        __syncthreads();

        // prefetch next K while softmax proceeds (K reads are done)
        if (it < SEQ / 128 - 1) { attn_ld_K(smb, qkb, (it + 1) * 128, tid); CP_COMMIT(); }

        float f8[8], mn8[8];
        #pragma unroll
        for (int mi = 0; mi < 4; mi++) {
            #pragma unroll
            for (int hf = 0; hf < 2; hf++) {
                int row = wm * 64 + mi * 16 + hf * 8 + g;
                float mx = fmaxf(fmaxf(sM[row][0], sM[row][1]), fmaxf(sM[row][2], sM[row][3]));
                float mn = fmaxf(m_run[mi * 2 + hf], mx);
                f8[mi * 2 + hf] = __expf(m_run[mi * 2 + hf] - mn);
                mn8[mi * 2 + hf] = mn;
                m_run[mi * 2 + hf] = mn;
            }
        }
        float ls[8];
        #pragma unroll
        for (int i = 0; i < 8; i++) ls[i] = 0.0f;
        #pragma unroll
        for (int mi = 0; mi < 4; mi++)
            #pragma unroll
            for (int ni = 0; ni < 4; ni++) {
                sacc[mi][ni][0] = __expf(sacc[mi][ni][0] - mn8[mi * 2]);
                sacc[mi][ni][1] = __expf(sacc[mi][ni][1] - mn8[mi * 2]);
                sacc[mi][ni][2] = __expf(sacc[mi][ni][2] - mn8[mi * 2 + 1]);
                sacc[mi][ni][3] = __expf(sacc[mi][ni][3] - mn8[mi * 2 + 1]);
                ls[mi * 2]     += sacc[mi][ni][0] + sacc[mi][ni][1];
                ls[mi * 2 + 1] += sacc[mi][ni][2] + sacc[mi][ni][3];
            }
        #pragma unroll
        for (int i = 0; i < 8; i++) {
            ls[i] += __shfl_xor_sync(0xffffffffu, ls[i], 1);
            ls[i] += __shfl_xor_sync(0xffffffffu, ls[i], 2);
        }
        if (t == 0) {
            #pragma unroll
            for (int mi = 0; mi < 4; mi++) {
                sL[wm * 64 + mi * 16 + g][wn]     = ls[mi * 2];
                sL[wm * 64 + mi * 16 + 8 + g][wn] = ls[mi * 2 + 1];
            }
        }

        // stage P (split bf16) to SMEM
        #pragma unroll
        for (int mi = 0; mi < 4; mi++) {
            int r0 = wm * 64 + mi * 16 + g;
            #pragma unroll
            for (int ni = 0; ni < 4; ni++) {
                int key = wn * 32 + ni * 8 + 2 * t;
                uint32_t ph, pl;
                split_pack(sacc[mi][ni][0], sacc[mi][ni][1], ph, pl);
                *(uint32_t*)&Ph[r0 * PP + key] = ph;
                *(uint32_t*)&Pl[r0 * PP + key] = pl;
                split_pack(sacc[mi][ni][2], sacc[mi][ni][3], ph, pl);
                *(uint32_t*)&Ph[(r0 + 8) * PP + key] = ph;
                *(uint32_t*)&Pl[(r0 + 8) * PP + key] = pl;
            }
        }
        __syncthreads();

        // l update + rescale ctx acc
        #pragma unroll
        for (int mi = 0; mi < 4; mi++)
            #pragma unroll
            for (int hf = 0; hf < 2; hf++) {
                int row = wm * 64 + mi * 16 + hf * 8 + g;
                float s4 = (sL[row][0] + sL[row][1]) + (sL[row][2] + sL[row][3]);
                l_run[mi * 2 + hf] = l_run[mi * 2 + hf] * f8[mi * 2 + hf] + s4;
            }
        #pragma unroll
        for (int mi = 0; mi < 4; mi++)
            #pragma unroll
            for (int ni = 0; ni < 2; ni++) {
                cacc[mi][ni][0] *= f8[mi * 2];
                cacc[mi][ni][1] *= f8[mi * 2];
                cacc[mi][ni][2] *= f8[mi * 2 + 1];
                cacc[mi][ni][3] *= f8[mi * 2 + 1];
            }

        // ---- ctx += P @ V (3-pass) ----
        #pragma unroll
        for (int ks = 0; ks < 8; ks++) {
            const int c = ks * 16 + 2 * t;
            uint32_t pa_h[4][4], pa_l[4][4], vb_h[2][2], vb_l[2][2];
            #pragma unroll
            for (int mi = 0; mi < 4; mi++) {
                int r0 = wm * 64 + mi * 16 + g;
                pa_h[mi][0] = *(const uint32_t*)&Ph[r0 * PP + c];
                pa_h[mi][1] = *(const uint32_t*)&Ph[(r0 + 8) * PP + c];
                pa_h[mi][2] = *(const uint32_t*)&Ph[r0 * PP + c + 8];
                pa_h[mi][3] = *(const uint32_t*)&Ph[(r0 + 8) * PP + c + 8];
                pa_l[mi][0] = *(const uint32_t*)&Pl[r0 * PP + c];
                pa_l[mi][1] = *(const uint32_t*)&Pl[(r0 + 8) * PP + c];
                pa_l[mi][2] = *(const uint32_t*)&Pl[r0 * PP + c + 8];
                pa_l[mi][3] = *(const uint32_t*)&Pl[(r0 + 8) * PP + c + 8];
            }
            #pragma unroll
            for (int ni = 0; ni < 2; ni++) {
                int rb = wn * 16 + ni * 8 + g;
                vb_h[ni][0] = *(const uint32_t*)&Vth[rb * VP + c];
                vb_h[ni][1] = *(const uint32_t*)&Vth[rb * VP + c + 8];
                vb_l[ni][0] = *(const uint32_t*)&Vtl[rb * VP + c];
                vb_l[ni][1] = *(const uint32_t*)&Vtl[rb * VP + c + 8];
            }
            #pragma unroll
            for (int mi = 0; mi < 4; mi++)
                #pragma unroll
                for (int ni = 0; ni < 2; ni++) {
                    mma_bf16(cacc[mi][ni], pa_h[mi], vb_h[ni]);
                    mma_bf16(cacc[mi][ni], pa_h[mi], vb_l[ni]);
                    mma_bf16(cacc[mi][ni], pa_l[mi], vb_h[ni]);
                }
        }
        __syncthreads();

        if (it < SEQ / 128 - 1) { attn_ld_V(smb, qkb, (it + 1) * 128, tid); CP_COMMIT(); }
    }

    // epilogue: ctx/l -> split bf16 [B][S][1024]
    const int b = bh >> 4;
    const int h = bh & 15;
    #pragma unroll
    for (int mi = 0; mi < 4; mi++) {
        #pragma unroll
        for (int hf = 0; hf < 2; hf++) {
            int row = q0 + wm * 64 + mi * 16 + hf * 8 + g;
            float inv = 1.0f / l_run[mi * 2 + hf];
            #pragma unroll
            for (int ni = 0; ni < 2; ni++) {
                int col = h * DH + wn * 16 + ni * 8 + 2 * t;
                size_t base = ((size_t)(b * SEQ) + row) * DMODEL + col;
                uint32_t ph, pl;
                split_pack(cacc[mi][ni][hf * 2] * inv, cacc[mi][ni][hf * 2 + 1] * inv, ph, pl);
                *(uint32_t*)&g_ch[base] = ph;
                *(uint32_t*)&g_cl[base] = pl;
            }
        }
    }
}

// ---------------------------------------------------------------------------
// Launch
// ---------------------------------------------------------------------------
extern "C" void kernel_launch(void* const* d_in, const int* in_sizes, int n_in,
                              void* d_out, int out_size)
{
    (void)in_sizes; (void)n_in; (void)out_size;
    const float* x  = (const float*)d_in[0];
    const float* Wk = (const float*)d_in[1];
    const float* Wq = (const float*)d_in[2];
    const float* Wv = (const float*)d_in[3];
    const float* Wo = (const float*)d_in[4];
    const float* bo = (const float*)d_in[5];
    float* out = (float*)d_out;

    cudaFuncSetAttribute(qkv_mma, cudaFuncAttributeMaxDynamicSharedMemorySize, MMA_SMEM);
    cudaFuncSetAttribute(out_mma, cudaFuncAttributeMaxDynamicSharedMemorySize, MMA_SMEM);
    cudaFuncSetAttribute(attn_mma, cudaFuncAttributeMaxDynamicSharedMemorySize, ATTN_SMEM);

    conv_wt<<<dim3(32, 32, 4), dim3(32, 8)>>>(Wq, Wk, Wv, Wo);
    conv_x_k<<<(MROWS * DMODEL / 4) / 256, 256>>>(x);

    qkv_mma<<<dim3(DMODEL / 128, MROWS / 128, 3), 256, MMA_SMEM>>>();

    attn_mma<<<dim3(SEQ / 128, NBATCH * NH), 256, ATTN_SMEM>>>();

    out_mma<<<dim3(DMODEL / 128, MROWS / 128), 256, MMA_SMEM>>>(bo, out);
}